// round 10
// baseline (speedup 1.0000x reference)
#include <cuda_runtime.h>
#include <cuda_bf16.h>
#include <math.h>

#define BB 4
#define SS 2048
#define DD 1024
#define HH 16
#define HDIM 64
#define NT (BB*SS)   // 8192 tokens
#define PG 40        // bf16 smem pitch (elems) = 80B rows, ldsm conflict-free
#define PK 72        // attention smem pitch (bf16)

// int8 quantization scales (power-of-2; product of cross scales = 2^22)
#define SA_X   16.f        // x / att full value
#define SAL_X  8192.f      // x / att bf16-residual
#define SB_W   512.f       // W full value
#define SBL_W  262144.f    // W bf16-residual
#define SCINV  (1.f/4194304.f)   // 2^-22

// ---- scratch (static device globals — allocation-free) ----
__device__ __nv_bfloat16 g_xh[(size_t)NT*DD];
__device__ signed char   g_x8[(size_t)NT*DD],  g_xl8[(size_t)NT*DD];
__device__ __nv_bfloat16 g_wh[4][(size_t)DD*DD];
__device__ signed char   g_w8[4][(size_t)DD*DD], g_wl8[4][(size_t)DD*DD];
__device__ __nv_bfloat16 g_Qh[(size_t)BB*HH*SS*HDIM], g_Ql[(size_t)BB*HH*SS*HDIM];
__device__ __nv_bfloat16 g_Kh[(size_t)BB*HH*SS*HDIM], g_Kl[(size_t)BB*HH*SS*HDIM];
__device__ __nv_bfloat16 g_Vh[(size_t)BB*HH*SS*HDIM], g_Vl[(size_t)BB*HH*SS*HDIM];
__device__ __nv_bfloat16 g_ah[(size_t)NT*DD];
__device__ signed char   g_a8[(size_t)NT*DD],  g_al8[(size_t)NT*DD];

#define MMA_BF16(d, a, b0, b1)                                             \
    asm("mma.sync.aligned.m16n8k16.row.col.f32.bf16.bf16.f32 "             \
        "{%0,%1,%2,%3}, {%4,%5,%6,%7}, {%8,%9}, {%0,%1,%2,%3};"            \
        : "+f"(d[0]), "+f"(d[1]), "+f"(d[2]), "+f"(d[3])                   \
        : "r"(a[0]), "r"(a[1]), "r"(a[2]), "r"(a[3]), "r"(b0), "r"(b1))

#define MMA_S8(d, a, b0, b1)                                               \
    asm("mma.sync.aligned.m16n8k32.row.col.s32.s8.s8.s32 "                 \
        "{%0,%1,%2,%3}, {%4,%5,%6,%7}, {%8,%9}, {%0,%1,%2,%3};"            \
        : "+r"(d[0]), "+r"(d[1]), "+r"(d[2]), "+r"(d[3])                   \
        : "r"(a[0]), "r"(a[1]), "r"(a[2]), "r"(a[3]), "r"(b0), "r"(b1))

__device__ __forceinline__ void ldsm4(unsigned* r, unsigned a) {
    asm volatile("ldmatrix.sync.aligned.m8n8.x4.shared.b16 {%0,%1,%2,%3}, [%4];"
                 : "=r"(r[0]), "=r"(r[1]), "=r"(r[2]), "=r"(r[3]) : "r"(a));
}
__device__ __forceinline__ void ldsm4t(unsigned* r, unsigned a) {
    asm volatile("ldmatrix.sync.aligned.m8n8.x4.trans.shared.b16 {%0,%1,%2,%3}, [%4];"
                 : "=r"(r[0]), "=r"(r[1]), "=r"(r[2]), "=r"(r[3]) : "r"(a));
}
__device__ __forceinline__ unsigned smem_u32(const void* p) {
    return (unsigned)__cvta_generic_to_shared(p);
}
__device__ __forceinline__ unsigned packbf(__nv_bfloat16 a, __nv_bfloat16 b) {
    __nv_bfloat162 t(a, b);
    return reinterpret_cast<unsigned&>(t);
}
__device__ __forceinline__ void split2(float a, float b, unsigned &h, unsigned &l) {
    __nv_bfloat16 h0 = __float2bfloat16(a), h1 = __float2bfloat16(b);
    h = packbf(h0, h1);
    l = packbf(__float2bfloat16(a - __bfloat162float(h0)),
               __float2bfloat16(b - __bfloat162float(h1)));
}
__device__ __forceinline__ int q8(float v, float s) {
    int r = __float2int_rn(v * s);
    return max(-127, min(127, r));
}
__device__ __forceinline__ void cpa16(unsigned dst, const void* src) {
    asm volatile("cp.async.cg.shared.global [%0], [%1], 16;" :: "r"(dst), "l"(src));
}
#define CP_COMMIT() asm volatile("cp.async.commit_group;")
#define CP_WAIT(N)  asm volatile("cp.async.wait_group %0;" :: "n"(N))

// ---------------------------------------------------------------------------
// Kernel 0: fused fp32 -> (bf16 hi, s8 full, s8 residual) of x + 4 weights.
// ---------------------------------------------------------------------------
__global__ __launch_bounds__(256) void cvt_all(
    const float* __restrict__ x,
    const float* __restrict__ Wq, const float* __restrict__ Wk,
    const float* __restrict__ Wv, const float* __restrict__ Wo)
{
    const size_t NX = (size_t)NT*DD;
    const size_t NW = (size_t)DD*DD;
    size_t i = ((size_t)blockIdx.x*256 + threadIdx.x) * 4;
    const float* src; __nv_bfloat16* dh; signed char *d8, *dl8; size_t off;
    float sA, sAl;
    if (i < NX) { src = x; dh = g_xh; d8 = g_x8; dl8 = g_xl8; off = i; sA = SA_X; sAl = SAL_X; }
    else {
        size_t j = i - NX;
        int w = (int)(j / NW);
        off = j - (size_t)w*NW;
        src = (w==0)?Wq:(w==1)?Wk:(w==2)?Wv:Wo;
        dh = g_wh[w]; d8 = g_w8[w]; dl8 = g_wl8[w];
        sA = SB_W; sAl = SBL_W;
    }
    float4 v = *(const float4*)&src[off];
    float va[4] = {v.x, v.y, v.z, v.w};
    unsigned h2[2];
    unsigned p8 = 0, pl8 = 0;
    #pragma unroll
    for (int e = 0; e < 2; ++e) {
        __nv_bfloat16 h0 = __float2bfloat16(va[2*e]);
        __nv_bfloat16 h1 = __float2bfloat16(va[2*e+1]);
        h2[e] = packbf(h0, h1);
        float r0 = va[2*e]   - __bfloat162float(h0);
        float r1 = va[2*e+1] - __bfloat162float(h1);
        p8  |= ((unsigned)(q8(va[2*e], sA)   & 255)) << (16*e);
        p8  |= ((unsigned)(q8(va[2*e+1], sA) & 255)) << (16*e + 8);
        pl8 |= ((unsigned)(q8(r0, sAl) & 255)) << (16*e);
        pl8 |= ((unsigned)(q8(r1, sAl) & 255)) << (16*e + 8);
    }
    *(uint2*)&dh[off] = make_uint2(h2[0], h2[1]);
    *(unsigned*)&d8[off]  = p8;
    *(unsigned*)&dl8[off] = pl8;
}

// ---------------------------------------------------------------------------
// GEMM mainloop: d = ah*bh (bf16) + 2^-22 * (a8*bl8 + al8*b8) (int8 k32)
// Tile 128M x 64N, k-chunk 32, 256 threads (8 warps x 16 rows).
// cp.async double-buffered.
// smem stage layout (bytes): AH[128*80] BH[64*80] A8[128*48] AL8[128*48]
//                            B8[64*48] BL8[64*48]
// ---------------------------------------------------------------------------
#define OFF_AH  0
#define OFF_BH  10240
#define OFF_A8  15360
#define OFF_AL8 21504
#define OFF_B8  27648
#define OFF_BL8 30720
#define STG5    33792
#define GSM5    (2*STG5)   // 67584

__device__ __forceinline__ void run_gemm5(
    const __nv_bfloat16* __restrict__ Agh, const signed char* __restrict__ Ag8,
    const signed char* __restrict__ Agl8,
    const __nv_bfloat16* __restrict__ Bgh, const signed char* __restrict__ Bg8,
    const signed char* __restrict__ Bgl8,
    int t0, int n0, unsigned sbase, float accB[8][4], int accC[8][4])
{
    const int tid  = threadIdx.x;
    const int lane = tid & 31;
    const int warp = tid >> 5;
    const int g = lane >> 3, lr = lane & 7;

    const unsigned aoff  = (unsigned)((warp*16 + (g&1)*8 + lr)*PG + (g>>1)*8) * 2;
    const unsigned boff  = (unsigned)(((g&1)*8 + lr)*PG + (g>>1)*8) * 2;
    const unsigned a8off = (unsigned)((warp*16 + (g&1)*8 + lr)*48 + (g>>1)*16);
    const unsigned b8off = (unsigned)(((g&1)*8 + lr)*48 + (g>>1)*16);

    auto issue = [&](int kc, int s) {
        const int k0 = kc * 32;
        const unsigned stg = sbase + (unsigned)s * STG5;
        #pragma unroll
        for (int p = 0; p < 2; ++p) {            // AH: 128 rows x 4x16B
            int idx = tid + p*256;
            int row = idx >> 2, c = idx & 3;
            cpa16(stg + OFF_AH + row*80 + c*16,
                  Agh + (size_t)(t0+row)*DD + k0 + c*8);
        }
        {                                        // BH: 64 rows x 4x16B
            int row = tid >> 2, c = tid & 3;
            cpa16(stg + OFF_BH + row*80 + c*16,
                  Bgh + (size_t)(n0+row)*DD + k0 + c*8);
        }
        {                                        // A8/AL8: 128 rows x 2x16B
            int row = tid >> 1, c = tid & 1;
            cpa16(stg + OFF_A8  + row*48 + c*16,
                  Ag8  + (size_t)(t0+row)*DD + k0 + c*16);
            cpa16(stg + OFF_AL8 + row*48 + c*16,
                  Agl8 + (size_t)(t0+row)*DD + k0 + c*16);
        }
        if (tid < 128) {                         // B8: 64 rows x 2x16B
            int row = tid >> 1, c = tid & 1;
            cpa16(stg + OFF_B8 + row*48 + c*16,
                  Bg8 + (size_t)(n0+row)*DD + k0 + c*16);
        } else {                                 // BL8
            int t2 = tid - 128;
            int row = t2 >> 1, c = t2 & 1;
            cpa16(stg + OFF_BL8 + row*48 + c*16,
                  Bgl8 + (size_t)(n0+row)*DD + k0 + c*16);
        }
    };

    issue(0, 0);
    CP_COMMIT();

    for (int kc = 0; kc < DD/32; ++kc) {
        const int s = kc & 1;
        if (kc + 1 < DD/32) {
            issue(kc + 1, s ^ 1);
            CP_COMMIT();
            CP_WAIT(1);
        } else {
            CP_WAIT(0);
        }
        __syncthreads();

        const unsigned stg = sbase + (unsigned)s * STG5;

        // ---- bf16 main product: 2 x k16 steps
        #pragma unroll
        for (int k16 = 0; k16 < 2; ++k16) {
            unsigned af[4], bf[4][4];
            ldsm4(af, stg + OFF_AH + aoff + k16*32);
            #pragma unroll
            for (int jp = 0; jp < 4; ++jp)
                ldsm4(bf[jp], stg + OFF_BH + boff + (unsigned)(jp*16*PG)*2 + k16*32);
            #pragma unroll
            for (int jp = 0; jp < 4; ++jp) {
                MMA_BF16(accB[2*jp],   af, bf[jp][0], bf[jp][2]);
                MMA_BF16(accB[2*jp+1], af, bf[jp][1], bf[jp][3]);
            }
        }

        // ---- int8 corrections: full k32 per MMA
        {
            unsigned a8f[4], al8f[4];
            ldsm4(a8f,  stg + OFF_A8  + a8off);
            ldsm4(al8f, stg + OFF_AL8 + a8off);
            #pragma unroll
            for (int jp = 0; jp < 4; ++jp) {
                unsigned b8f[4], bl8f[4];
                ldsm4(b8f,  stg + OFF_B8  + b8off + (unsigned)(jp*16*48));
                ldsm4(bl8f, stg + OFF_BL8 + b8off + (unsigned)(jp*16*48));
                MMA_S8(accC[2*jp],   a8f,  bl8f[0], bl8f[2]);   // a * bl
                MMA_S8(accC[2*jp],   al8f, b8f[0],  b8f[2]);    // al * b
                MMA_S8(accC[2*jp+1], a8f,  bl8f[1], bl8f[3]);
                MMA_S8(accC[2*jp+1], al8f, b8f[1],  b8f[3]);
            }
        }
        __syncthreads();
    }
}

// ---------------------------------------------------------------------------
// Kernel 1: QKV projections + bias + fused RoPE -> bf16 hi/lo [b,h,s,hd].
// grid = (NT/128, DD/64, 3)
// ---------------------------------------------------------------------------
__global__ __launch_bounds__(256) void qkv_gemm(
    const float* __restrict__ bq, const float* __restrict__ bk,
    const float* __restrict__ bv,
    const float* __restrict__ cosT, const float* __restrict__ sinT)
{
    extern __shared__ __align__(16) char dsm[];
    const unsigned sbase = smem_u32(dsm);

    const int z = blockIdx.z;
    const float* __restrict__ bp = (z==0) ? bq : (z==1) ? bk : bv;
    __nv_bfloat16* __restrict__ dh = (z==0) ? g_Qh : (z==1) ? g_Kh : g_Vh;
    __nv_bfloat16* __restrict__ dl = (z==0) ? g_Ql : (z==1) ? g_Kl : g_Vl;

    const int t0 = blockIdx.x * 128;
    const int n0 = blockIdx.y * 64;
    const int lane = threadIdx.x & 31;
    const int warp = threadIdx.x >> 5;

    float accB[8][4] = {};
    int   accC[8][4] = {};
    run_gemm5(g_xh, g_x8, g_xl8, g_wh[z], g_w8[z], g_wl8[z], t0, n0, sbase, accB, accC);

    float acc[8][4];
    #pragma unroll
    for (int j = 0; j < 8; ++j)
        #pragma unroll
        for (int c = 0; c < 4; ++c)
            acc[j][c] = accB[j][c] + (float)accC[j][c] * SCINV;

    const int h = n0 >> 6;
    float2 bia[8];
    #pragma unroll
    for (int j = 0; j < 8; ++j)
        bia[j] = *(const float2*)&bp[n0 + j*8 + (lane & 3)*2];

    const int r0 = t0 + warp*16 + (lane >> 2);
    #pragma unroll
    for (int half = 0; half < 2; ++half) {
        int t = r0 + half * 8;
        int b = t >> 11;
        int s = t & (SS - 1);
        size_t base = (((size_t)b*HH + h)*SS + s) * HDIM;
        if (z < 2) {
            #pragma unroll
            for (int j = 0; j < 4; ++j) {
                int ch = j*8 + (lane & 3)*2;          // < 32
                float v0a = acc[j  ][2*half]   + bia[j].x;
                float v0b = acc[j  ][2*half+1] + bia[j].y;
                float v1a = acc[j+4][2*half]   + bia[j+4].x;
                float v1b = acc[j+4][2*half+1] + bia[j+4].y;
                float2 c0 = *(const float2*)&cosT[s*HDIM + ch];
                float2 s0 = *(const float2*)&sinT[s*HDIM + ch];
                float2 c1 = *(const float2*)&cosT[s*HDIM + ch + 32];
                float2 s1 = *(const float2*)&sinT[s*HDIM + ch + 32];
                unsigned hh, ll;
                split2(v0a*c0.x - v1a*s0.x, v0b*c0.y - v1b*s0.y, hh, ll);
                *(unsigned*)&dh[base + ch] = hh;
                *(unsigned*)&dl[base + ch] = ll;
                split2(v1a*c1.x + v0a*s1.x, v1b*c1.y + v0b*s1.y, hh, ll);
                *(unsigned*)&dh[base + ch + 32] = hh;
                *(unsigned*)&dl[base + ch + 32] = ll;
            }
        } else {
            #pragma unroll
            for (int j = 0; j < 8; ++j) {
                int ch = j*8 + (lane & 3)*2;          // < 64
                unsigned hh, ll;
                split2(acc[j][2*half] + bia[j].x,
                       acc[j][2*half+1] + bia[j].y, hh, ll);
                *(unsigned*)&dh[base + ch] = hh;
                *(unsigned*)&dl[base + ch] = ll;
            }
        }
    }
}

// ---------------------------------------------------------------------------
// Kernel 3: output projection -> d_out [t, n] fp32. grid = (NT/128, DD/64)
// ---------------------------------------------------------------------------
__global__ __launch_bounds__(256) void out_gemm(
    const float* __restrict__ bo, float* __restrict__ out)
{
    extern __shared__ __align__(16) char dsm[];
    const unsigned sbase = smem_u32(dsm);

    const int t0 = blockIdx.x * 128;
    const int n0 = blockIdx.y * 64;
    const int lane = threadIdx.x & 31;
    const int warp = threadIdx.x >> 5;

    float accB[8][4] = {};
    int   accC[8][4] = {};
    run_gemm5(g_ah, g_a8, g_al8, g_wh[3], g_w8[3], g_wl8[3], t0, n0, sbase, accB, accC);

    float2 bia[8];
    #pragma unroll
    for (int j = 0; j < 8; ++j)
        bia[j] = *(const float2*)&bo[n0 + j*8 + (lane & 3)*2];

    const int r0 = t0 + warp*16 + (lane >> 2);
    #pragma unroll
    for (int half = 0; half < 2; ++half) {
        int t = r0 + half * 8;
        #pragma unroll
        for (int j = 0; j < 8; ++j) {
            int n = n0 + j*8 + (lane & 3)*2;
            float2 o;
            o.x = accB[j][2*half]   + (float)accC[j][2*half]   * SCINV + bia[j].x;
            o.y = accB[j][2*half+1] + (float)accC[j][2*half+1] * SCINV + bia[j].y;
            *(float2*)&out[(size_t)t*DD + n] = o;
        }
    }
}

// ---------------------------------------------------------------------------
// Kernel 2: flash causal attention, bf16 hi/lo (mainloop unchanged from R9).
// Epilogue writes att as (bf16 hi, s8 full, s8 residual).
// ---------------------------------------------------------------------------
__global__ __launch_bounds__(256, 2) void attn_mma()
{
    extern __shared__ __align__(16) __nv_bfloat16 smb[];
    __nv_bfloat16* Qh = smb;               // [128][PK]
    __nv_bfloat16* Ql = Qh + 128*PK;
    __nv_bfloat16* Kh = Ql + 128*PK;       // [64][PK]
    __nv_bfloat16* Kl = Kh + 64*PK;
    __nv_bfloat16* Vh = Kl + 64*PK;        // [64][PK]
    __nv_bfloat16* Vl = Vh + 64*PK;

    const int tid  = threadIdx.x;
    const int lane = tid & 31;
    const int warp = tid >> 5;
    const int bh = blockIdx.y;
    const int qt = gridDim.x - 1 - blockIdx.x;   // long tiles first
    const int q0 = qt * 128;

    const size_t hb = (size_t)bh * SS * HDIM;

    #pragma unroll
    for (int p = 0; p < 4; ++p) {
        int idx = tid + p*256;
        int row = idx >> 3, c8 = idx & 7;
        *(uint4*)&Qh[row*PK + c8*8] = *(const uint4*)&g_Qh[hb + (size_t)(q0+row)*HDIM + c8*8];
        *(uint4*)&Ql[row*PK + c8*8] = *(const uint4*)&g_Ql[hb + (size_t)(q0+row)*HDIM + c8*8];
    }

    const int g = lane >> 3, lr = lane & 7;
    const unsigned aQoff = (unsigned)((warp*16 + (g&1)*8 + lr)*PK + (g>>1)*8) * 2;
    const unsigned adQh = smem_u32(Qh) + aQoff;
    const unsigned adQl = smem_u32(Ql) + aQoff;
    const unsigned bKoff = (unsigned)(((g&1)*8 + lr)*PK + (g>>1)*8) * 2;
    const unsigned adKh = smem_u32(Kh) + bKoff;
    const unsigned adKl = smem_u32(Kl) + bKoff;
    const unsigned adVh = smem_u32(Vh) + bKoff;
    const unsigned adVl = smem_u32(Vl) + bKoff;

    float O[8][4] = {};
    float m0 = -1e30f, m1 = -1e30f, l0 = 0.f, l1 = 0.f;
    const float C = 0.18033688011112042f;   // (1/8) * log2(e)

    const int nkb = 2*qt + 2;
    for (int kb = 0; kb < nkb; ++kb) {
        const int k0 = kb * 64;
        __syncthreads();
        #pragma unroll
        for (int p = 0; p < 2; ++p) {
            int idx = tid + p*256;
            int row = idx >> 3, c8 = idx & 7;
            size_t go = hb + (size_t)(k0+row)*HDIM + c8*8;
            *(uint4*)&Kh[row*PK + c8*8] = *(const uint4*)&g_Kh[go];
            *(uint4*)&Kl[row*PK + c8*8] = *(const uint4*)&g_Kl[go];
            *(uint4*)&Vh[row*PK + c8*8] = *(const uint4*)&g_Vh[go];
            *(uint4*)&Vl[row*PK + c8*8] = *(const uint4*)&g_Vl[go];
        }
        __syncthreads();

        float z[8][4] = {};
        #pragma unroll
        for (int k16 = 0; k16 < 4; ++k16) {
            unsigned qh[4], ql[4];
            ldsm4(qh, adQh + k16*32);
            ldsm4(ql, adQl + k16*32);
            #pragma unroll
            for (int jp = 0; jp < 4; ++jp) {
                unsigned kh[4], kl[4];
                const unsigned off = (unsigned)(jp*16*PK + k16*16) * 2;
                ldsm4(kh, adKh + off);
                ldsm4(kl, adKl + off);
                MMA_BF16(z[2*jp],   qh, kh[0], kh[2]);
                MMA_BF16(z[2*jp],   qh, kl[0], kl[2]);
                MMA_BF16(z[2*jp],   ql, kh[0], kh[2]);
                MMA_BF16(z[2*jp+1], qh, kh[1], kh[3]);
                MMA_BF16(z[2*jp+1], qh, kl[1], kl[3]);
                MMA_BF16(z[2*jp+1], ql, kh[1], kh[3]);
            }
        }

        const bool tail = (kb >= 2*qt);
        #pragma unroll
        for (int j = 0; j < 8; ++j) {
            #pragma unroll
            for (int c = 0; c < 4; ++c) {
                int key = k0 + j*8 + (lane & 3)*2 + (c & 1);
                int row = q0 + warp*16 + (lane >> 2) + (c >> 1)*8;
                z[j][c] = (tail && key > row) ? -1e30f : z[j][c]*C;
            }
        }

        float ml0 = -1e30f, ml1 = -1e30f;
        #pragma unroll
        for (int j = 0; j < 8; ++j) {
            ml0 = fmaxf(ml0, fmaxf(z[j][0], z[j][1]));
            ml1 = fmaxf(ml1, fmaxf(z[j][2], z[j][3]));
        }
        ml0 = fmaxf(ml0, __shfl_xor_sync(0xffffffffu, ml0, 1));
        ml0 = fmaxf(ml0, __shfl_xor_sync(0xffffffffu, ml0, 2));
        ml1 = fmaxf(ml1, __shfl_xor_sync(0xffffffffu, ml1, 1));
        ml1 = fmaxf(ml1, __shfl_xor_sync(0xffffffffu, ml1, 2));
        float mn0 = fmaxf(m0, ml0), mn1 = fmaxf(m1, ml1);
        float al0 = exp2f(m0 - mn0), al1 = exp2f(m1 - mn1);
        m0 = mn0; m1 = mn1;

        float rs0 = 0.f, rs1 = 0.f;
        #pragma unroll
        for (int j = 0; j < 8; ++j) {
            z[j][0] = exp2f(z[j][0] - mn0);
            z[j][1] = exp2f(z[j][1] - mn0);
            z[j][2] = exp2f(z[j][2] - mn1);
            z[j][3] = exp2f(z[j][3] - mn1);
            rs0 += z[j][0] + z[j][1];
            rs1 += z[j][2] + z[j][3];
        }
        rs0 += __shfl_xor_sync(0xffffffffu, rs0, 1);
        rs0 += __shfl_xor_sync(0xffffffffu, rs0, 2);
        rs1 += __shfl_xor_sync(0xffffffffu, rs1, 1);
        rs1 += __shfl_xor_sync(0xffffffffu, rs1, 2);
        l0 = l0*al0 + rs0;
        l1 = l1*al1 + rs1;
        #pragma unroll
        for (int j = 0; j < 8; ++j) {
            O[j][0] *= al0; O[j][1] *= al0;
            O[j][2] *= al1; O[j][3] *= al1;
        }

        #pragma unroll
        for (int k16 = 0; k16 < 4; ++k16) {
            const int f0 = 2*k16, f1 = 2*k16 + 1;
            unsigned ah[4], alr[4];
            split2(z[f0][0], z[f0][1], ah[0], alr[0]);
            split2(z[f0][2], z[f0][3], ah[1], alr[1]);
            split2(z[f1][0], z[f1][1], ah[2], alr[2]);
            split2(z[f1][2], z[f1][3], ah[3], alr[3]);
            #pragma unroll
            for (int jp = 0; jp < 4; ++jp) {
                unsigned vh[4], vl[4];
                const unsigned off = (unsigned)(k16*16*PK + jp*16) * 2;
                ldsm4t(vh, adVh + off);
                ldsm4t(vl, adVl + off);
                MMA_BF16(O[2*jp],   ah,  vh[0], vh[1]);
                MMA_BF16(O[2*jp],   ah,  vl[0], vl[1]);
                MMA_BF16(O[2*jp],   alr, vh[0], vh[1]);
                MMA_BF16(O[2*jp+1], ah,  vh[2], vh[3]);
                MMA_BF16(O[2*jp+1], ah,  vl[2], vl[3]);
                MMA_BF16(O[2*jp+1], alr, vh[2], vh[3]);
            }
        }
    }

    // ---- normalize + write att as (bf16 hi, s8 full, s8 residual) [t, d]
    const int b = bh >> 4;
    const int h = bh & 15;
    const float inv0 = 1.f / l0, inv1 = 1.f / l1;
    const int rlo = q0 + warp*16 + (lane >> 2);
    #pragma unroll
    for (int j = 0; j < 8; ++j) {
        int hd = h*HDIM + j*8 + (lane & 3)*2;
        #pragma unroll
        for (int half = 0; half < 2; ++half) {
            float o0 = O[j][2*half]   * (half ? inv1 : inv0);
            float o1 = O[j][2*half+1] * (half ? inv1 : inv0);
            size_t ix = ((size_t)(b*SS + rlo + half*8))*DD + hd;
            __nv_bfloat16 h0 = __float2bfloat16(o0);
            __nv_bfloat16 h1 = __float2bfloat16(o1);
            *(unsigned*)&g_ah[ix] = packbf(h0, h1);
            int u0 = q8(o0, SA_X), u1 = q8(o1, SA_X);
            *(short*)&g_a8[ix] = (short)((u0 & 0xFF) | ((u1 & 0xFF) << 8));
            float r0 = o0 - __bfloat162float(h0);
            float r1 = o1 - __bfloat162float(h1);
            u0 = q8(r0, SAL_X); u1 = q8(r1, SAL_X);
            *(short*)&g_al8[ix] = (short)((u0 & 0xFF) | ((u1 & 0xFF) << 8));
        }
    }
}

// ---------------------------------------------------------------------------
extern "C" void kernel_launch(void* const* d_in, const int* in_sizes, int n_in,
                              void* d_out, int out_size)
{
    const float* x    = (const float*)d_in[0];
    const float* cosT = (const float*)d_in[1];
    const float* sinT = (const float*)d_in[2];
    // d_in[3] = attn_mask (causal — applied analytically)
    const float* Wq = (const float*)d_in[4];
    const float* bq = (const float*)d_in[5];
    const float* Wk = (const float*)d_in[6];
    const float* bk = (const float*)d_in[7];
    const float* Wv = (const float*)d_in[8];
    const float* bv = (const float*)d_in[9];
    const float* Wo = (const float*)d_in[10];
    const float* bo = (const float*)d_in[11];
    float* out = (float*)d_out;

    // 0) fused fp32 -> (bf16 hi, s8, s8-residual) split
    const size_t ntotal = (size_t)NT*DD + 4*(size_t)DD*DD;
    cvt_all<<<(int)(ntotal/1024), 256>>>(x, Wq, Wk, Wv, Wo);

    // 1) QKV + RoPE (bf16 main + int8 corrections)
    cudaFuncSetAttribute(qkv_gemm, cudaFuncAttributeMaxDynamicSharedMemorySize, GSM5);
    qkv_gemm<<<dim3(NT/128, DD/64, 3), 256, GSM5>>>(bq, bk, bv, cosT, sinT);

    // 2) causal flash attention
    size_t asm_ = (size_t)(2*128*PK + 4*64*PK) * sizeof(__nv_bfloat16);  // 73728
    cudaFuncSetAttribute(attn_mma, cudaFuncAttributeMaxDynamicSharedMemorySize, (int)asm_);
    attn_mma<<<dim3(SS/128, BB*HH), 256, asm_>>>();

    // 3) output projection
    cudaFuncSetAttribute(out_gemm, cudaFuncAttributeMaxDynamicSharedMemorySize, GSM5);
    out_gemm<<<dim3(NT/128, DD/64), 256, GSM5>>>(bo, out);
}

// round 11
// speedup vs baseline: 3.8830x; 3.8830x over previous
#include <cuda_runtime.h>
#include <cuda_fp16.h>
#include <math.h>

#define BB 4
#define SS 2048
#define DD 1024
#define HH 16
#define HDIM 64
#define NT (BB*SS)   // 8192 tokens
#define PG 40        // gemm smem pitch (fp16 elems) = 80B rows, ldsm conflict-free
#define PK 72        // attention smem pitch (fp16 elems)

// ---- fp16 scratch (static device globals — allocation-free) ----
__device__ __half g_xf[(size_t)NT*DD];
__device__ __half g_wf[4][(size_t)DD*DD];            // Wq,Wk,Wv,Wo
__device__ __half g_Qf[(size_t)BB*HH*SS*HDIM];
__device__ __half g_Kf[(size_t)BB*HH*SS*HDIM];
__device__ __half g_Vf[(size_t)BB*HH*SS*HDIM];
__device__ __half g_af[(size_t)NT*DD];               // att [t,d]

#define MMA_F16(d, a, b0, b1)                                              \
    asm("mma.sync.aligned.m16n8k16.row.col.f32.f16.f16.f32 "               \
        "{%0,%1,%2,%3}, {%4,%5,%6,%7}, {%8,%9}, {%0,%1,%2,%3};"            \
        : "+f"(d[0]), "+f"(d[1]), "+f"(d[2]), "+f"(d[3])                   \
        : "r"(a[0]), "r"(a[1]), "r"(a[2]), "r"(a[3]), "r"(b0), "r"(b1))

__device__ __forceinline__ void ldsm4(unsigned* r, unsigned a) {
    asm volatile("ldmatrix.sync.aligned.m8n8.x4.shared.b16 {%0,%1,%2,%3}, [%4];"
                 : "=r"(r[0]), "=r"(r[1]), "=r"(r[2]), "=r"(r[3]) : "r"(a));
}
__device__ __forceinline__ void ldsm4t(unsigned* r, unsigned a) {
    asm volatile("ldmatrix.sync.aligned.m8n8.x4.trans.shared.b16 {%0,%1,%2,%3}, [%4];"
                 : "=r"(r[0]), "=r"(r[1]), "=r"(r[2]), "=r"(r[3]) : "r"(a));
}
__device__ __forceinline__ unsigned smem_u32(const void* p) {
    return (unsigned)__cvta_generic_to_shared(p);
}
__device__ __forceinline__ unsigned packh(float a, float b) {
    __half2 t = __floats2half2_rn(a, b);
    return reinterpret_cast<unsigned&>(t);
}
__device__ __forceinline__ void cpa16(unsigned dst, const void* src) {
    asm volatile("cp.async.cg.shared.global [%0], [%1], 16;" :: "r"(dst), "l"(src));
}
#define CP_COMMIT() asm volatile("cp.async.commit_group;")
#define CP_WAIT(N)  asm volatile("cp.async.wait_group %0;" :: "n"(N))

// ---------------------------------------------------------------------------
// Kernel 0: fused fp32 -> fp16 of x + 4 weights.
// ---------------------------------------------------------------------------
__global__ __launch_bounds__(256) void cvt_all(
    const float* __restrict__ x,
    const float* __restrict__ Wq, const float* __restrict__ Wk,
    const float* __restrict__ Wv, const float* __restrict__ Wo)
{
    const size_t NX = (size_t)NT*DD;
    const size_t NW = (size_t)DD*DD;
    size_t i = ((size_t)blockIdx.x*256 + threadIdx.x) * 4;
    const float* src; __half* df; size_t off;
    if (i < NX) { src = x; df = g_xf; off = i; }
    else {
        size_t j = i - NX;
        int w = (int)(j / NW);
        off = j - (size_t)w*NW;
        src = (w==0)?Wq:(w==1)?Wk:(w==2)?Wv:Wo;
        df = g_wf[w];
    }
    float4 v = *(const float4*)&src[off];
    *(uint2*)&df[off] = make_uint2(packh(v.x, v.y), packh(v.z, v.w));
}

// ---------------------------------------------------------------------------
// fp16 single-product GEMM mainloop: out[t0+m, n0+n] = sum_k A[.,k]*B[.,k]
// Tile 128M x 128N, k-chunk 32, 256 threads (8 warps: 4M x 2N, warp 32x64).
// cp.async double-buffered. acc[2][8][4] fp32.
// ---------------------------------------------------------------------------
#define OFF_B6  (128*PG*2)            // 10240
#define STG6    (2*128*PG*2)          // 20480
#define GSM6    (2*STG6)              // 40960

__device__ __forceinline__ void run_gemm6(
    const __half* __restrict__ Af, const __half* __restrict__ Bf,
    int t0, int n0, unsigned sbase, float acc[2][8][4])
{
    const int tid  = threadIdx.x;
    const int lane = tid & 31;
    const int warp = tid >> 5;
    const int wm   = warp & 3;
    const int wn   = warp >> 2;
    const int g = lane >> 3, lr = lane & 7;

    const unsigned aoff0 = (unsigned)((wm*32 +      (g&1)*8 + lr)*PG + (g>>1)*8) * 2;
    const unsigned aoff1 = (unsigned)((wm*32 + 16 + (g&1)*8 + lr)*PG + (g>>1)*8) * 2;
    const unsigned boff  = (unsigned)((wn*64 + (g&1)*8 + lr)*PG + (g>>1)*8) * 2;

    auto issue = [&](int kc, int s) {
        const int k0 = kc * 32;
        const unsigned stg = sbase + (unsigned)s * STG6;
        #pragma unroll
        for (int p = 0; p < 2; ++p) {
            int idx = tid + p*256;
            int row = idx >> 2, c = idx & 3;      // 128 rows x 4x16B
            cpa16(stg + (unsigned)(row*PG + c*8)*2,
                  Af + (size_t)(t0+row)*DD + k0 + c*8);
            cpa16(stg + OFF_B6 + (unsigned)(row*PG + c*8)*2,
                  Bf + (size_t)(n0+row)*DD + k0 + c*8);
        }
    };

    issue(0, 0);
    CP_COMMIT();

    for (int kc = 0; kc < DD/32; ++kc) {
        const int s = kc & 1;
        if (kc + 1 < DD/32) {
            issue(kc + 1, s ^ 1);
            CP_COMMIT();
            CP_WAIT(1);
        } else {
            CP_WAIT(0);
        }
        __syncthreads();

        const unsigned stg = sbase + (unsigned)s * STG6;
        #pragma unroll
        for (int k16 = 0; k16 < 2; ++k16) {
            unsigned af0[4], af1[4];
            ldsm4(af0, stg + aoff0 + k16*32);
            ldsm4(af1, stg + aoff1 + k16*32);
            #pragma unroll
            for (int jp = 0; jp < 4; ++jp) {
                unsigned bf[4];
                ldsm4(bf, stg + OFF_B6 + boff + (unsigned)(jp*16*PG)*2 + k16*32);
                MMA_F16(acc[0][2*jp],   af0, bf[0], bf[2]);
                MMA_F16(acc[0][2*jp+1], af0, bf[1], bf[3]);
                MMA_F16(acc[1][2*jp],   af1, bf[0], bf[2]);
                MMA_F16(acc[1][2*jp+1], af1, bf[1], bf[3]);
            }
        }
        __syncthreads();
    }
}

// ---------------------------------------------------------------------------
// Kernel 1: QKV projections + bias + fused RoPE -> fp16 [b,h,s,hd].
// grid = (NT/128, DD/128, 3)
// ---------------------------------------------------------------------------
__global__ __launch_bounds__(256, 2) void qkv_gemm(
    const float* __restrict__ bq, const float* __restrict__ bk,
    const float* __restrict__ bv,
    const float* __restrict__ cosT, const float* __restrict__ sinT)
{
    extern __shared__ __align__(16) char dsm[];
    const unsigned sbase = smem_u32(dsm);

    const int z = blockIdx.z;
    const float* __restrict__ bp = (z==0) ? bq : (z==1) ? bk : bv;
    __half* __restrict__ df = (z==0) ? g_Qf : (z==1) ? g_Kf : g_Vf;

    const int t0 = blockIdx.x * 128;
    const int n0 = blockIdx.y * 128;
    const int lane = threadIdx.x & 31;
    const int warp = threadIdx.x >> 5;
    const int wm = warp & 3, wn = warp >> 2;

    float acc[2][8][4] = {};
    run_gemm6(g_xf, g_wf[z], t0, n0, sbase, acc);

    const int h = (n0 + wn*64) >> 6;     // warp's 64-col slice == one head
    float2 bia[8];
    #pragma unroll
    for (int j = 0; j < 8; ++j)
        bia[j] = *(const float2*)&bp[n0 + wn*64 + j*8 + (lane & 3)*2];

    #pragma unroll
    for (int am = 0; am < 2; ++am) {
        const int r0 = t0 + wm*32 + am*16 + (lane >> 2);
        #pragma unroll
        for (int half = 0; half < 2; ++half) {
            int t = r0 + half * 8;
            int b = t >> 11;
            int s = t & (SS - 1);
            size_t base = (((size_t)b*HH + h)*SS + s) * HDIM;
            if (z < 2) {
                #pragma unroll
                for (int j = 0; j < 4; ++j) {
                    int ch = j*8 + (lane & 3)*2;          // < 32
                    float v0a = acc[am][j  ][2*half]   + bia[j].x;
                    float v0b = acc[am][j  ][2*half+1] + bia[j].y;
                    float v1a = acc[am][j+4][2*half]   + bia[j+4].x;
                    float v1b = acc[am][j+4][2*half+1] + bia[j+4].y;
                    float2 c0 = *(const float2*)&cosT[s*HDIM + ch];
                    float2 s0 = *(const float2*)&sinT[s*HDIM + ch];
                    float2 c1 = *(const float2*)&cosT[s*HDIM + ch + 32];
                    float2 s1 = *(const float2*)&sinT[s*HDIM + ch + 32];
                    *(unsigned*)&df[base + ch]      = packh(v0a*c0.x - v1a*s0.x,
                                                            v0b*c0.y - v1b*s0.y);
                    *(unsigned*)&df[base + ch + 32] = packh(v1a*c1.x + v0a*s1.x,
                                                            v1b*c1.y + v0b*s1.y);
                }
            } else {
                #pragma unroll
                for (int j = 0; j < 8; ++j) {
                    int ch = j*8 + (lane & 3)*2;          // < 64
                    *(unsigned*)&df[base + ch] = packh(acc[am][j][2*half]   + bia[j].x,
                                                       acc[am][j][2*half+1] + bia[j].y);
                }
            }
        }
    }
}

// ---------------------------------------------------------------------------
// Kernel 3: output projection -> d_out [t, n] fp32. grid = (NT/128, DD/128)
// ---------------------------------------------------------------------------
__global__ __launch_bounds__(256, 2) void out_gemm(
    const float* __restrict__ bo, float* __restrict__ out)
{
    extern __shared__ __align__(16) char dsm[];
    const unsigned sbase = smem_u32(dsm);

    const int t0 = blockIdx.x * 128;
    const int n0 = blockIdx.y * 128;
    const int lane = threadIdx.x & 31;
    const int warp = threadIdx.x >> 5;
    const int wm = warp & 3, wn = warp >> 2;

    float acc[2][8][4] = {};
    run_gemm6(g_af, g_wf[3], t0, n0, sbase, acc);

    float2 bia[8];
    #pragma unroll
    for (int j = 0; j < 8; ++j)
        bia[j] = *(const float2*)&bo[n0 + wn*64 + j*8 + (lane & 3)*2];

    #pragma unroll
    for (int am = 0; am < 2; ++am) {
        const int r0 = t0 + wm*32 + am*16 + (lane >> 2);
        #pragma unroll
        for (int half = 0; half < 2; ++half) {
            int t = r0 + half * 8;
            #pragma unroll
            for (int j = 0; j < 8; ++j) {
                int n = n0 + wn*64 + j*8 + (lane & 3)*2;
                float2 o;
                o.x = acc[am][j][2*half]   + bia[j].x;
                o.y = acc[am][j][2*half+1] + bia[j].y;
                *(float2*)&out[(size_t)t*DD + n] = o;
            }
        }
    }
}

// ---------------------------------------------------------------------------
// Kernel 2: flash causal attention, fp16 single product.
// 128q tile (8 warps x 16 rows) x 64k blocks. grid = (16, 64).
// ---------------------------------------------------------------------------
__global__ __launch_bounds__(256, 2) void attn_mma()
{
    extern __shared__ __align__(16) __half smh[];
    __half* Qf = smh;                  // [128][PK]
    __half* Kf = Qf + 128*PK;          // [64][PK]
    __half* Vf = Kf + 64*PK;           // [64][PK]

    const int tid  = threadIdx.x;
    const int lane = tid & 31;
    const int warp = tid >> 5;
    const int bh = blockIdx.y;
    const int qt = gridDim.x - 1 - blockIdx.x;   // long tiles first
    const int q0 = qt * 128;

    const size_t hb = (size_t)bh * SS * HDIM;

    // ---- load Q tile: 128 rows x 64 halfs (8 uint4 per row)
    #pragma unroll
    for (int p = 0; p < 4; ++p) {
        int idx = tid + p*256;
        int row = idx >> 3, c8 = idx & 7;
        *(uint4*)&Qf[row*PK + c8*8] = *(const uint4*)&g_Qf[hb + (size_t)(q0+row)*HDIM + c8*8];
    }

    const int g = lane >> 3, lr = lane & 7;
    const unsigned adQ = smem_u32(Qf) + (unsigned)((warp*16 + (g&1)*8 + lr)*PK + (g>>1)*8) * 2;
    const unsigned bKoff = (unsigned)(((g&1)*8 + lr)*PK + (g>>1)*8) * 2;
    const unsigned adK = smem_u32(Kf) + bKoff;
    const unsigned adV = smem_u32(Vf) + bKoff;

    float O[8][4] = {};
    float m0 = -1e30f, m1 = -1e30f, l0 = 0.f, l1 = 0.f;
    const float C = 0.18033688011112042f;   // (1/8) * log2(e)

    const int nkb = 2*qt + 2;
    for (int kb = 0; kb < nkb; ++kb) {
        const int k0 = kb * 64;
        __syncthreads();
        // ---- load K,V block: 64 rows x 8 uint4 each
        #pragma unroll
        for (int p = 0; p < 2; ++p) {
            int idx = tid + p*256;
            int row = idx >> 3, c8 = idx & 7;
            size_t go = hb + (size_t)(k0+row)*HDIM + c8*8;
            *(uint4*)&Kf[row*PK + c8*8] = *(const uint4*)&g_Kf[go];
            *(uint4*)&Vf[row*PK + c8*8] = *(const uint4*)&g_Vf[go];
        }
        __syncthreads();

        // ---- S = Q K^T (single fp16 product)
        float z[8][4] = {};
        #pragma unroll
        for (int k16 = 0; k16 < 4; ++k16) {
            unsigned qf[4];
            ldsm4(qf, adQ + k16*32);
            #pragma unroll
            for (int jp = 0; jp < 4; ++jp) {
                unsigned kf[4];
                ldsm4(kf, adK + (unsigned)(jp*16*PK)*2 + k16*32);
                MMA_F16(z[2*jp],   qf, kf[0], kf[2]);
                MMA_F16(z[2*jp+1], qf, kf[1], kf[3]);
            }
        }

        // ---- scale (log2 domain) + causal mask (boundary blocks only)
        const bool tail = (kb >= 2*qt);
        #pragma unroll
        for (int j = 0; j < 8; ++j) {
            #pragma unroll
            for (int c = 0; c < 4; ++c) {
                int key = k0 + j*8 + (lane & 3)*2 + (c & 1);
                int row = q0 + warp*16 + (lane >> 2) + (c >> 1)*8;
                z[j][c] = (tail && key > row) ? -1e30f : z[j][c]*C;
            }
        }

        // ---- online softmax
        float ml0 = -1e30f, ml1 = -1e30f;
        #pragma unroll
        for (int j = 0; j < 8; ++j) {
            ml0 = fmaxf(ml0, fmaxf(z[j][0], z[j][1]));
            ml1 = fmaxf(ml1, fmaxf(z[j][2], z[j][3]));
        }
        ml0 = fmaxf(ml0, __shfl_xor_sync(0xffffffffu, ml0, 1));
        ml0 = fmaxf(ml0, __shfl_xor_sync(0xffffffffu, ml0, 2));
        ml1 = fmaxf(ml1, __shfl_xor_sync(0xffffffffu, ml1, 1));
        ml1 = fmaxf(ml1, __shfl_xor_sync(0xffffffffu, ml1, 2));
        float mn0 = fmaxf(m0, ml0), mn1 = fmaxf(m1, ml1);
        float al0 = exp2f(m0 - mn0), al1 = exp2f(m1 - mn1);
        m0 = mn0; m1 = mn1;

        float rs0 = 0.f, rs1 = 0.f;
        #pragma unroll
        for (int j = 0; j < 8; ++j) {
            z[j][0] = exp2f(z[j][0] - mn0);
            z[j][1] = exp2f(z[j][1] - mn0);
            z[j][2] = exp2f(z[j][2] - mn1);
            z[j][3] = exp2f(z[j][3] - mn1);
            rs0 += z[j][0] + z[j][1];
            rs1 += z[j][2] + z[j][3];
        }
        rs0 += __shfl_xor_sync(0xffffffffu, rs0, 1);
        rs0 += __shfl_xor_sync(0xffffffffu, rs0, 2);
        rs1 += __shfl_xor_sync(0xffffffffu, rs1, 1);
        rs1 += __shfl_xor_sync(0xffffffffu, rs1, 2);
        l0 = l0*al0 + rs0;
        l1 = l1*al1 + rs1;
        #pragma unroll
        for (int j = 0; j < 8; ++j) {
            O[j][0] *= al0; O[j][1] *= al0;
            O[j][2] *= al1; O[j][3] *= al1;
        }

        // ---- O += P V (single fp16 product; P packed in registers)
        #pragma unroll
        for (int k16 = 0; k16 < 4; ++k16) {
            const int f0 = 2*k16, f1 = 2*k16 + 1;
            unsigned ah[4];
            ah[0] = packh(z[f0][0], z[f0][1]);
            ah[1] = packh(z[f0][2], z[f0][3]);
            ah[2] = packh(z[f1][0], z[f1][1]);
            ah[3] = packh(z[f1][2], z[f1][3]);
            #pragma unroll
            for (int jp = 0; jp < 4; ++jp) {
                unsigned vf[4];
                ldsm4t(vf, adV + (unsigned)(k16*16*PK + jp*16)*2);
                MMA_F16(O[2*jp],   ah, vf[0], vf[1]);
                MMA_F16(O[2*jp+1], ah, vf[2], vf[3]);
            }
        }
    }

    // ---- normalize + write att fp16 [t, d]
    const int b = bh >> 4;
    const int h = bh & 15;
    const float inv0 = 1.f / l0, inv1 = 1.f / l1;
    const int rlo = q0 + warp*16 + (lane >> 2);
    #pragma unroll
    for (int j = 0; j < 8; ++j) {
        int hd = h*HDIM + j*8 + (lane & 3)*2;
        *(unsigned*)&g_af[((size_t)(b*SS + rlo    ))*DD + hd] = packh(O[j][0]*inv0, O[j][1]*inv0);
        *(unsigned*)&g_af[((size_t)(b*SS + rlo + 8))*DD + hd] = packh(O[j][2]*inv1, O[j][3]*inv1);
    }
}

// ---------------------------------------------------------------------------
extern "C" void kernel_launch(void* const* d_in, const int* in_sizes, int n_in,
                              void* d_out, int out_size)
{
    const float* x    = (const float*)d_in[0];
    const float* cosT = (const float*)d_in[1];
    const float* sinT = (const float*)d_in[2];
    // d_in[3] = attn_mask (causal — applied analytically)
    const float* Wq = (const float*)d_in[4];
    const float* bq = (const float*)d_in[5];
    const float* Wk = (const float*)d_in[6];
    const float* bk = (const float*)d_in[7];
    const float* Wv = (const float*)d_in[8];
    const float* bv = (const float*)d_in[9];
    const float* Wo = (const float*)d_in[10];
    const float* bo = (const float*)d_in[11];
    float* out = (float*)d_out;

    // 0) fused fp32 -> fp16
    const size_t ntotal = (size_t)NT*DD + 4*(size_t)DD*DD;
    cvt_all<<<(int)(ntotal/1024), 256>>>(x, Wq, Wk, Wv, Wo);

    // 1) QKV + RoPE (fp16 single product)
    cudaFuncSetAttribute(qkv_gemm, cudaFuncAttributeMaxDynamicSharedMemorySize, GSM6);
    qkv_gemm<<<dim3(NT/128, DD/128, 3), 256, GSM6>>>(bq, bk, bv, cosT, sinT);

    // 2) causal flash attention (fp16 single product)
    size_t asm_ = (size_t)(128*PK + 64*PK + 64*PK) * sizeof(__half);  // 36864
    cudaFuncSetAttribute(attn_mma, cudaFuncAttributeMaxDynamicSharedMemorySize, (int)asm_);
    attn_mma<<<dim3(SS/128, BB*HH), 256, asm_>>>();

    // 3) output projection
    cudaFuncSetAttribute(out_gemm, cudaFuncAttributeMaxDynamicSharedMemorySize, GSM6);
    out_gemm<<<dim3(NT/128, DD/128), 256, GSM6>>>(bo, out);
}

// round 12
// speedup vs baseline: 4.1545x; 1.0699x over previous
#include <cuda_runtime.h>
#include <cuda_fp16.h>
#include <math.h>

#define BB 4
#define SS 2048
#define DD 1024
#define HH 16
#define HDIM 64
#define NT (BB*SS)   // 8192 tokens
#define P2 72        // smem pitch (fp16 elems) = 144B rows, ldsm conflict-free

// ---- fp16 scratch (static device globals — allocation-free) ----
__device__ __half g_xf[(size_t)NT*DD];
__device__ __half g_wf[4][(size_t)DD*DD];            // Wq,Wk,Wv,Wo
__device__ __half g_Qf[(size_t)BB*HH*SS*HDIM];
__device__ __half g_Kf[(size_t)BB*HH*SS*HDIM];
__device__ __half g_Vf[(size_t)BB*HH*SS*HDIM];
__device__ __half g_af[(size_t)NT*DD];               // att [t,d]

#define MMA_F16(d, a, b0, b1)                                              \
    asm("mma.sync.aligned.m16n8k16.row.col.f32.f16.f16.f32 "               \
        "{%0,%1,%2,%3}, {%4,%5,%6,%7}, {%8,%9}, {%0,%1,%2,%3};"            \
        : "+f"(d[0]), "+f"(d[1]), "+f"(d[2]), "+f"(d[3])                   \
        : "r"(a[0]), "r"(a[1]), "r"(a[2]), "r"(a[3]), "r"(b0), "r"(b1))

__device__ __forceinline__ void ldsm4(unsigned* r, unsigned a) {
    asm volatile("ldmatrix.sync.aligned.m8n8.x4.shared.b16 {%0,%1,%2,%3}, [%4];"
                 : "=r"(r[0]), "=r"(r[1]), "=r"(r[2]), "=r"(r[3]) : "r"(a));
}
__device__ __forceinline__ void ldsm4t(unsigned* r, unsigned a) {
    asm volatile("ldmatrix.sync.aligned.m8n8.x4.trans.shared.b16 {%0,%1,%2,%3}, [%4];"
                 : "=r"(r[0]), "=r"(r[1]), "=r"(r[2]), "=r"(r[3]) : "r"(a));
}
__device__ __forceinline__ unsigned smem_u32(const void* p) {
    return (unsigned)__cvta_generic_to_shared(p);
}
__device__ __forceinline__ unsigned packh(float a, float b) {
    __half2 t = __floats2half2_rn(a, b);
    return reinterpret_cast<unsigned&>(t);
}
__device__ __forceinline__ void cpa16(unsigned dst, const void* src) {
    asm volatile("cp.async.cg.shared.global [%0], [%1], 16;" :: "r"(dst), "l"(src));
}
#define CP_COMMIT() asm volatile("cp.async.commit_group;")
#define CP_WAIT(N)  asm volatile("cp.async.wait_group %0;" :: "n"(N))

// ---------------------------------------------------------------------------
// Kernel 0: fused fp32 -> fp16 of x + 4 weights.
// ---------------------------------------------------------------------------
__global__ __launch_bounds__(256) void cvt_all(
    const float* __restrict__ x,
    const float* __restrict__ Wq, const float* __restrict__ Wk,
    const float* __restrict__ Wv, const float* __restrict__ Wo)
{
    const size_t NX = (size_t)NT*DD;
    const size_t NW = (size_t)DD*DD;
    size_t i = ((size_t)blockIdx.x*256 + threadIdx.x) * 4;
    const float* src; __half* df; size_t off;
    if (i < NX) { src = x; df = g_xf; off = i; }
    else {
        size_t j = i - NX;
        int w = (int)(j / NW);
        off = j - (size_t)w*NW;
        src = (w==0)?Wq:(w==1)?Wk:(w==2)?Wv:Wo;
        df = g_wf[w];
    }
    float4 v = *(const float4*)&src[off];
    *(uint2*)&df[off] = make_uint2(packh(v.x, v.y), packh(v.z, v.w));
}

// ---------------------------------------------------------------------------
// fp16 GEMM mainloop: out[t0+m, n0+n] = sum_k A[.,k]*B[.,k]
// Tile 128M x 128N, k-chunk 64 (4 k16 steps per barrier pair).
// 256 threads (8 warps: 4M x 2N, warp 32x64). cp.async double-buffered.
// ---------------------------------------------------------------------------
#define OFF_B7  (128*P2*2)            // 18432
#define STG7    (2*128*P2*2)          // 36864
#define GSM7    (2*STG7)              // 73728

__device__ __forceinline__ void run_gemm7(
    const __half* __restrict__ Af, const __half* __restrict__ Bf,
    int t0, int n0, unsigned sbase, float acc[2][8][4])
{
    const int tid  = threadIdx.x;
    const int lane = tid & 31;
    const int warp = tid >> 5;
    const int wm   = warp & 3;
    const int wn   = warp >> 2;
    const int g = lane >> 3, lr = lane & 7;

    const unsigned aoff0 = (unsigned)((wm*32 +      (g&1)*8 + lr)*P2 + (g>>1)*8) * 2;
    const unsigned aoff1 = (unsigned)((wm*32 + 16 + (g&1)*8 + lr)*P2 + (g>>1)*8) * 2;
    const unsigned boff  = (unsigned)((wn*64 + (g&1)*8 + lr)*P2 + (g>>1)*8) * 2;

    auto issue = [&](int kc, int s) {
        const int k0 = kc * 64;
        const unsigned stg = sbase + (unsigned)s * STG7;
        #pragma unroll
        for (int p = 0; p < 4; ++p) {
            int idx = tid + p*256;
            int row = idx >> 3, c = idx & 7;      // 128 rows x 8x16B
            cpa16(stg + (unsigned)(row*P2 + c*8)*2,
                  Af + (size_t)(t0+row)*DD + k0 + c*8);
            cpa16(stg + OFF_B7 + (unsigned)(row*P2 + c*8)*2,
                  Bf + (size_t)(n0+row)*DD + k0 + c*8);
        }
    };

    issue(0, 0);
    CP_COMMIT();

    for (int kc = 0; kc < DD/64; ++kc) {
        const int s = kc & 1;
        if (kc + 1 < DD/64) {
            issue(kc + 1, s ^ 1);
            CP_COMMIT();
            CP_WAIT(1);
        } else {
            CP_WAIT(0);
        }
        __syncthreads();

        const unsigned stg = sbase + (unsigned)s * STG7;
        #pragma unroll
        for (int k16 = 0; k16 < 4; ++k16) {
            unsigned af0[4], af1[4];
            ldsm4(af0, stg + aoff0 + k16*32);
            ldsm4(af1, stg + aoff1 + k16*32);
            #pragma unroll
            for (int jp = 0; jp < 4; ++jp) {
                unsigned bf[4];
                ldsm4(bf, stg + OFF_B7 + boff + (unsigned)(jp*16*P2)*2 + k16*32);
                MMA_F16(acc[0][2*jp],   af0, bf[0], bf[2]);
                MMA_F16(acc[0][2*jp+1], af0, bf[1], bf[3]);
                MMA_F16(acc[1][2*jp],   af1, bf[0], bf[2]);
                MMA_F16(acc[1][2*jp+1], af1, bf[1], bf[3]);
            }
        }
        __syncthreads();
    }
}

// ---------------------------------------------------------------------------
// Kernel 1: QKV projections + bias + fused RoPE -> fp16 [b,h,s,hd].
// grid = (NT/128, DD/128, 3)
// ---------------------------------------------------------------------------
__global__ __launch_bounds__(256, 2) void qkv_gemm(
    const float* __restrict__ bq, const float* __restrict__ bk,
    const float* __restrict__ bv,
    const float* __restrict__ cosT, const float* __restrict__ sinT)
{
    extern __shared__ __align__(16) char dsm[];
    const unsigned sbase = smem_u32(dsm);

    const int z = blockIdx.z;
    const float* __restrict__ bp = (z==0) ? bq : (z==1) ? bk : bv;
    __half* __restrict__ df = (z==0) ? g_Qf : (z==1) ? g_Kf : g_Vf;

    const int t0 = blockIdx.x * 128;
    const int n0 = blockIdx.y * 128;
    const int lane = threadIdx.x & 31;
    const int warp = threadIdx.x >> 5;
    const int wm = warp & 3, wn = warp >> 2;

    float acc[2][8][4] = {};
    run_gemm7(g_xf, g_wf[z], t0, n0, sbase, acc);

    const int h = (n0 + wn*64) >> 6;     // warp's 64-col slice == one head
    float2 bia[8];
    #pragma unroll
    for (int j = 0; j < 8; ++j)
        bia[j] = *(const float2*)&bp[n0 + wn*64 + j*8 + (lane & 3)*2];

    #pragma unroll
    for (int am = 0; am < 2; ++am) {
        const int r0 = t0 + wm*32 + am*16 + (lane >> 2);
        #pragma unroll
        for (int half = 0; half < 2; ++half) {
            int t = r0 + half * 8;
            int b = t >> 11;
            int s = t & (SS - 1);
            size_t base = (((size_t)b*HH + h)*SS + s) * HDIM;
            if (z < 2) {
                #pragma unroll
                for (int j = 0; j < 4; ++j) {
                    int ch = j*8 + (lane & 3)*2;          // < 32
                    float v0a = acc[am][j  ][2*half]   + bia[j].x;
                    float v0b = acc[am][j  ][2*half+1] + bia[j].y;
                    float v1a = acc[am][j+4][2*half]   + bia[j+4].x;
                    float v1b = acc[am][j+4][2*half+1] + bia[j+4].y;
                    float2 c0 = *(const float2*)&cosT[s*HDIM + ch];
                    float2 s0 = *(const float2*)&sinT[s*HDIM + ch];
                    float2 c1 = *(const float2*)&cosT[s*HDIM + ch + 32];
                    float2 s1 = *(const float2*)&sinT[s*HDIM + ch + 32];
                    *(unsigned*)&df[base + ch]      = packh(v0a*c0.x - v1a*s0.x,
                                                            v0b*c0.y - v1b*s0.y);
                    *(unsigned*)&df[base + ch + 32] = packh(v1a*c1.x + v0a*s1.x,
                                                            v1b*c1.y + v0b*s1.y);
                }
            } else {
                #pragma unroll
                for (int j = 0; j < 8; ++j) {
                    int ch = j*8 + (lane & 3)*2;          // < 64
                    *(unsigned*)&df[base + ch] = packh(acc[am][j][2*half]   + bia[j].x,
                                                       acc[am][j][2*half+1] + bia[j].y);
                }
            }
        }
    }
}

// ---------------------------------------------------------------------------
// Kernel 3: output projection -> d_out [t, n] fp32. grid = (NT/128, DD/128)
// ---------------------------------------------------------------------------
__global__ __launch_bounds__(256, 2) void out_gemm(
    const float* __restrict__ bo, float* __restrict__ out)
{
    extern __shared__ __align__(16) char dsm[];
    const unsigned sbase = smem_u32(dsm);

    const int t0 = blockIdx.x * 128;
    const int n0 = blockIdx.y * 128;
    const int lane = threadIdx.x & 31;
    const int warp = threadIdx.x >> 5;
    const int wm = warp & 3, wn = warp >> 2;

    float acc[2][8][4] = {};
    run_gemm7(g_af, g_wf[3], t0, n0, sbase, acc);

    float2 bia[8];
    #pragma unroll
    for (int j = 0; j < 8; ++j)
        bia[j] = *(const float2*)&bo[n0 + wn*64 + j*8 + (lane & 3)*2];

    #pragma unroll
    for (int am = 0; am < 2; ++am) {
        const int r0 = t0 + wm*32 + am*16 + (lane >> 2);
        #pragma unroll
        for (int half = 0; half < 2; ++half) {
            int t = r0 + half * 8;
            #pragma unroll
            for (int j = 0; j < 8; ++j) {
                int n = n0 + wn*64 + j*8 + (lane & 3)*2;
                float2 o;
                o.x = acc[am][j][2*half]   + bia[j].x;
                o.y = acc[am][j][2*half+1] + bia[j].y;
                *(float2*)&out[(size_t)t*DD + n] = o;
            }
        }
    }
}

// ---------------------------------------------------------------------------
// Kernel 2: flash causal attention, fp16 single product.
// 128q tile (8 warps x 16 rows); K/V loaded in 128-key superblocks,
// computed as two 64-key halves (barriers amortized 2x). grid = (16, 64).
// ---------------------------------------------------------------------------
__global__ __launch_bounds__(256, 2) void attn_mma()
{
    extern __shared__ __align__(16) __half smh[];
    __half* Qf = smh;                  // [128][P2]
    __half* Kf = Qf + 128*P2;          // [128][P2]
    __half* Vf = Kf + 128*P2;          // [128][P2]

    const int tid  = threadIdx.x;
    const int lane = tid & 31;
    const int warp = tid >> 5;
    const int bh = blockIdx.y;
    const int qt = gridDim.x - 1 - blockIdx.x;   // long tiles first
    const int q0 = qt * 128;

    const size_t hb = (size_t)bh * SS * HDIM;

    // ---- load Q tile: 128 rows x 64 halfs
    #pragma unroll
    for (int p = 0; p < 4; ++p) {
        int idx = tid + p*256;
        int row = idx >> 3, c8 = idx & 7;
        *(uint4*)&Qf[row*P2 + c8*8] = *(const uint4*)&g_Qf[hb + (size_t)(q0+row)*HDIM + c8*8];
    }

    const int g = lane >> 3, lr = lane & 7;
    const unsigned adQ = smem_u32(Qf) + (unsigned)((warp*16 + (g&1)*8 + lr)*P2 + (g>>1)*8) * 2;
    const unsigned bKoff = (unsigned)(((g&1)*8 + lr)*P2 + (g>>1)*8) * 2;
    const unsigned adK = smem_u32(Kf) + bKoff;
    const unsigned adV = smem_u32(Vf) + bKoff;

    float O[8][4] = {};
    float m0 = -1e30f, m1 = -1e30f, l0 = 0.f, l1 = 0.f;
    const float C = 0.18033688011112042f;   // (1/8) * log2(e)

    const int nkb = 2*qt + 2;               // 64-key blocks
    for (int kb2 = 0; kb2 <= qt; ++kb2) {   // 128-key superblocks
        const int k0s = kb2 * 128;
        __syncthreads();
        // ---- load K,V superblock: 128 rows x 8 uint4 each
        #pragma unroll
        for (int p = 0; p < 4; ++p) {
            int idx = tid + p*256;
            int row = idx >> 3, c8 = idx & 7;
            size_t go = hb + (size_t)(k0s+row)*HDIM + c8*8;
            *(uint4*)&Kf[row*P2 + c8*8] = *(const uint4*)&g_Kf[go];
            *(uint4*)&Vf[row*P2 + c8*8] = *(const uint4*)&g_Vf[go];
        }
        __syncthreads();

        #pragma unroll
        for (int h2 = 0; h2 < 2; ++h2) {
            const int kb = 2*kb2 + h2;
            const int k0 = kb * 64;
            const unsigned kvo = (unsigned)(h2*64*P2) * 2;

            // ---- S = Q K^T
            float z[8][4] = {};
            #pragma unroll
            for (int k16 = 0; k16 < 4; ++k16) {
                unsigned qf[4];
                ldsm4(qf, adQ + k16*32);
                #pragma unroll
                for (int jp = 0; jp < 4; ++jp) {
                    unsigned kf[4];
                    ldsm4(kf, adK + kvo + (unsigned)(jp*16*P2)*2 + k16*32);
                    MMA_F16(z[2*jp],   qf, kf[0], kf[2]);
                    MMA_F16(z[2*jp+1], qf, kf[1], kf[3]);
                }
            }

            // ---- scale (log2 domain) + causal mask (boundary blocks only)
            const bool tail = (kb >= 2*qt);
            #pragma unroll
            for (int j = 0; j < 8; ++j) {
                #pragma unroll
                for (int c = 0; c < 4; ++c) {
                    int key = k0 + j*8 + (lane & 3)*2 + (c & 1);
                    int row = q0 + warp*16 + (lane >> 2) + (c >> 1)*8;
                    z[j][c] = (tail && key > row) ? -1e30f : z[j][c]*C;
                }
            }

            // ---- online softmax
            float ml0 = -1e30f, ml1 = -1e30f;
            #pragma unroll
            for (int j = 0; j < 8; ++j) {
                ml0 = fmaxf(ml0, fmaxf(z[j][0], z[j][1]));
                ml1 = fmaxf(ml1, fmaxf(z[j][2], z[j][3]));
            }
            ml0 = fmaxf(ml0, __shfl_xor_sync(0xffffffffu, ml0, 1));
            ml0 = fmaxf(ml0, __shfl_xor_sync(0xffffffffu, ml0, 2));
            ml1 = fmaxf(ml1, __shfl_xor_sync(0xffffffffu, ml1, 1));
            ml1 = fmaxf(ml1, __shfl_xor_sync(0xffffffffu, ml1, 2));
            float mn0 = fmaxf(m0, ml0), mn1 = fmaxf(m1, ml1);
            float al0 = exp2f(m0 - mn0), al1 = exp2f(m1 - mn1);
            m0 = mn0; m1 = mn1;

            float rs0 = 0.f, rs1 = 0.f;
            #pragma unroll
            for (int j = 0; j < 8; ++j) {
                z[j][0] = exp2f(z[j][0] - mn0);
                z[j][1] = exp2f(z[j][1] - mn0);
                z[j][2] = exp2f(z[j][2] - mn1);
                z[j][3] = exp2f(z[j][3] - mn1);
                rs0 += z[j][0] + z[j][1];
                rs1 += z[j][2] + z[j][3];
            }
            rs0 += __shfl_xor_sync(0xffffffffu, rs0, 1);
            rs0 += __shfl_xor_sync(0xffffffffu, rs0, 2);
            rs1 += __shfl_xor_sync(0xffffffffu, rs1, 1);
            rs1 += __shfl_xor_sync(0xffffffffu, rs1, 2);
            l0 = l0*al0 + rs0;
            l1 = l1*al1 + rs1;
            #pragma unroll
            for (int j = 0; j < 8; ++j) {
                O[j][0] *= al0; O[j][1] *= al0;
                O[j][2] *= al1; O[j][3] *= al1;
            }

            // ---- O += P V (P packed in registers)
            #pragma unroll
            for (int k16 = 0; k16 < 4; ++k16) {
                const int f0 = 2*k16, f1 = 2*k16 + 1;
                unsigned ah[4];
                ah[0] = packh(z[f0][0], z[f0][1]);
                ah[1] = packh(z[f0][2], z[f0][3]);
                ah[2] = packh(z[f1][0], z[f1][1]);
                ah[3] = packh(z[f1][2], z[f1][3]);
                #pragma unroll
                for (int jp = 0; jp < 4; ++jp) {
                    unsigned vf[4];
                    ldsm4t(vf, adV + kvo + (unsigned)(k16*16*P2 + jp*16)*2);
                    MMA_F16(O[2*jp],   ah, vf[0], vf[1]);
                    MMA_F16(O[2*jp+1], ah, vf[2], vf[3]);
                }
            }
        }
    }

    // ---- normalize + write att fp16 [t, d]
    const int b = bh >> 4;
    const int h = bh & 15;
    const float inv0 = 1.f / l0, inv1 = 1.f / l1;
    const int rlo = q0 + warp*16 + (lane >> 2);
    #pragma unroll
    for (int j = 0; j < 8; ++j) {
        int hd = h*HDIM + j*8 + (lane & 3)*2;
        *(unsigned*)&g_af[((size_t)(b*SS + rlo    ))*DD + hd] = packh(O[j][0]*inv0, O[j][1]*inv0);
        *(unsigned*)&g_af[((size_t)(b*SS + rlo + 8))*DD + hd] = packh(O[j][2]*inv1, O[j][3]*inv1);
    }
}

// ---------------------------------------------------------------------------
extern "C" void kernel_launch(void* const* d_in, const int* in_sizes, int n_in,
                              void* d_out, int out_size)
{
    const float* x    = (const float*)d_in[0];
    const float* cosT = (const float*)d_in[1];
    const float* sinT = (const float*)d_in[2];
    // d_in[3] = attn_mask (causal — applied analytically)
    const float* Wq = (const float*)d_in[4];
    const float* bq = (const float*)d_in[5];
    const float* Wk = (const float*)d_in[6];
    const float* bk = (const float*)d_in[7];
    const float* Wv = (const float*)d_in[8];
    const float* bv = (const float*)d_in[9];
    const float* Wo = (const float*)d_in[10];
    const float* bo = (const float*)d_in[11];
    float* out = (float*)d_out;

    // 0) fused fp32 -> fp16
    const size_t ntotal = (size_t)NT*DD + 4*(size_t)DD*DD;
    cvt_all<<<(int)(ntotal/1024), 256>>>(x, Wq, Wk, Wv, Wo);

    // 1) QKV + RoPE
    cudaFuncSetAttribute(qkv_gemm, cudaFuncAttributeMaxDynamicSharedMemorySize, GSM7);
    qkv_gemm<<<dim3(NT/128, DD/128, 3), 256, GSM7>>>(bq, bk, bv, cosT, sinT);

    // 2) causal flash attention (128-key superblocks)
    size_t asm_ = (size_t)(3*128*P2) * sizeof(__half);   // 55296
    cudaFuncSetAttribute(attn_mma, cudaFuncAttributeMaxDynamicSharedMemorySize, (int)asm_);
    attn_mma<<<dim3(SS/128, BB*HH), 256, asm_>>>();

    // 3) output projection
    cudaFuncSetAttribute(out_gemm, cudaFuncAttributeMaxDynamicSharedMemorySize, GSM7);
    out_gemm<<<dim3(NT/128, DD/128), 256, GSM7>>>(bo, out);
}

// round 13
// speedup vs baseline: 4.2607x; 1.0256x over previous
#include <cuda_runtime.h>
#include <cuda_fp16.h>
#include <math.h>

#define BB 4
#define SS 2048
#define DD 1024
#define HH 16
#define HDIM 64
#define NT (BB*SS)   // 8192 tokens
#define P2 72        // smem pitch (fp16 elems) = 144B rows, ldsm conflict-free

// ---- fp16 scratch (static device globals — allocation-free) ----
__device__ __half g_xf[(size_t)NT*DD];
__device__ __half g_wf[4][(size_t)DD*DD];            // Wq,Wk,Wv,Wo
__device__ __half g_Qf[(size_t)BB*HH*SS*HDIM];
__device__ __half g_Kf[(size_t)BB*HH*SS*HDIM];
__device__ __half g_Vf[(size_t)BB*HH*SS*HDIM];
__device__ __half g_af[(size_t)NT*DD];               // att [t,d]

#define MMA_F16(d, a, b0, b1)                                              \
    asm("mma.sync.aligned.m16n8k16.row.col.f32.f16.f16.f32 "               \
        "{%0,%1,%2,%3}, {%4,%5,%6,%7}, {%8,%9}, {%0,%1,%2,%3};"            \
        : "+f"(d[0]), "+f"(d[1]), "+f"(d[2]), "+f"(d[3])                   \
        : "r"(a[0]), "r"(a[1]), "r"(a[2]), "r"(a[3]), "r"(b0), "r"(b1))

__device__ __forceinline__ void ldsm4(unsigned* r, unsigned a) {
    asm volatile("ldmatrix.sync.aligned.m8n8.x4.shared.b16 {%0,%1,%2,%3}, [%4];"
                 : "=r"(r[0]), "=r"(r[1]), "=r"(r[2]), "=r"(r[3]) : "r"(a));
}
__device__ __forceinline__ void ldsm4t(unsigned* r, unsigned a) {
    asm volatile("ldmatrix.sync.aligned.m8n8.x4.trans.shared.b16 {%0,%1,%2,%3}, [%4];"
                 : "=r"(r[0]), "=r"(r[1]), "=r"(r[2]), "=r"(r[3]) : "r"(a));
}
__device__ __forceinline__ unsigned smem_u32(const void* p) {
    return (unsigned)__cvta_generic_to_shared(p);
}
__device__ __forceinline__ unsigned packh(float a, float b) {
    __half2 t = __floats2half2_rn(a, b);
    return reinterpret_cast<unsigned&>(t);
}
__device__ __forceinline__ void cpa16(unsigned dst, const void* src) {
    asm volatile("cp.async.cg.shared.global [%0], [%1], 16;" :: "r"(dst), "l"(src));
}
#define CP_COMMIT() asm volatile("cp.async.commit_group;")
#define CP_WAIT(N)  asm volatile("cp.async.wait_group %0;" :: "n"(N))

// ---------------------------------------------------------------------------
// Kernel 0: fused fp32 -> fp16 of x + 4 weights.
// ---------------------------------------------------------------------------
__global__ __launch_bounds__(256) void cvt_all(
    const float* __restrict__ x,
    const float* __restrict__ Wq, const float* __restrict__ Wk,
    const float* __restrict__ Wv, const float* __restrict__ Wo)
{
    const size_t NX = (size_t)NT*DD;
    const size_t NW = (size_t)DD*DD;
    size_t i = ((size_t)blockIdx.x*256 + threadIdx.x) * 4;
    const float* src; __half* df; size_t off;
    if (i < NX) { src = x; df = g_xf; off = i; }
    else {
        size_t j = i - NX;
        int w = (int)(j / NW);
        off = j - (size_t)w*NW;
        src = (w==0)?Wq:(w==1)?Wk:(w==2)?Wv:Wo;
        df = g_wf[w];
    }
    float4 v = *(const float4*)&src[off];
    *(uint2*)&df[off] = make_uint2(packh(v.x, v.y), packh(v.z, v.w));
}

// ---------------------------------------------------------------------------
// fp16 GEMM mainloop (unchanged from R12): 128M x 128N tile, k-chunk 64.
// ---------------------------------------------------------------------------
#define OFF_B7  (128*P2*2)            // 18432
#define STG7    (2*128*P2*2)          // 36864
#define GSM7    (2*STG7)              // 73728

__device__ __forceinline__ void run_gemm7(
    const __half* __restrict__ Af, const __half* __restrict__ Bf,
    int t0, int n0, unsigned sbase, float acc[2][8][4])
{
    const int tid  = threadIdx.x;
    const int lane = tid & 31;
    const int warp = tid >> 5;
    const int wm   = warp & 3;
    const int wn   = warp >> 2;
    const int g = lane >> 3, lr = lane & 7;

    const unsigned aoff0 = (unsigned)((wm*32 +      (g&1)*8 + lr)*P2 + (g>>1)*8) * 2;
    const unsigned aoff1 = (unsigned)((wm*32 + 16 + (g&1)*8 + lr)*P2 + (g>>1)*8) * 2;
    const unsigned boff  = (unsigned)((wn*64 + (g&1)*8 + lr)*P2 + (g>>1)*8) * 2;

    auto issue = [&](int kc, int s) {
        const int k0 = kc * 64;
        const unsigned stg = sbase + (unsigned)s * STG7;
        #pragma unroll
        for (int p = 0; p < 4; ++p) {
            int idx = tid + p*256;
            int row = idx >> 3, c = idx & 7;      // 128 rows x 8x16B
            cpa16(stg + (unsigned)(row*P2 + c*8)*2,
                  Af + (size_t)(t0+row)*DD + k0 + c*8);
            cpa16(stg + OFF_B7 + (unsigned)(row*P2 + c*8)*2,
                  Bf + (size_t)(n0+row)*DD + k0 + c*8);
        }
    };

    issue(0, 0);
    CP_COMMIT();

    for (int kc = 0; kc < DD/64; ++kc) {
        const int s = kc & 1;
        if (kc + 1 < DD/64) {
            issue(kc + 1, s ^ 1);
            CP_COMMIT();
            CP_WAIT(1);
        } else {
            CP_WAIT(0);
        }
        __syncthreads();

        const unsigned stg = sbase + (unsigned)s * STG7;
        #pragma unroll
        for (int k16 = 0; k16 < 4; ++k16) {
            unsigned af0[4], af1[4];
            ldsm4(af0, stg + aoff0 + k16*32);
            ldsm4(af1, stg + aoff1 + k16*32);
            #pragma unroll
            for (int jp = 0; jp < 4; ++jp) {
                unsigned bf[4];
                ldsm4(bf, stg + OFF_B7 + boff + (unsigned)(jp*16*P2)*2 + k16*32);
                MMA_F16(acc[0][2*jp],   af0, bf[0], bf[2]);
                MMA_F16(acc[0][2*jp+1], af0, bf[1], bf[3]);
                MMA_F16(acc[1][2*jp],   af1, bf[0], bf[2]);
                MMA_F16(acc[1][2*jp+1], af1, bf[1], bf[3]);
            }
        }
        __syncthreads();
    }
}

// ---------------------------------------------------------------------------
// Kernel 1: QKV projections + bias + fused RoPE -> fp16 [b,h,s,hd].
// grid = (NT/128, DD/128, 3)
// ---------------------------------------------------------------------------
__global__ __launch_bounds__(256, 2) void qkv_gemm(
    const float* __restrict__ bq, const float* __restrict__ bk,
    const float* __restrict__ bv,
    const float* __restrict__ cosT, const float* __restrict__ sinT)
{
    extern __shared__ __align__(16) char dsm[];
    const unsigned sbase = smem_u32(dsm);

    const int z = blockIdx.z;
    const float* __restrict__ bp = (z==0) ? bq : (z==1) ? bk : bv;
    __half* __restrict__ df = (z==0) ? g_Qf : (z==1) ? g_Kf : g_Vf;

    const int t0 = blockIdx.x * 128;
    const int n0 = blockIdx.y * 128;
    const int lane = threadIdx.x & 31;
    const int warp = threadIdx.x >> 5;
    const int wm = warp & 3, wn = warp >> 2;

    float acc[2][8][4] = {};
    run_gemm7(g_xf, g_wf[z], t0, n0, sbase, acc);

    const int h = (n0 + wn*64) >> 6;     // warp's 64-col slice == one head
    float2 bia[8];
    #pragma unroll
    for (int j = 0; j < 8; ++j)
        bia[j] = *(const float2*)&bp[n0 + wn*64 + j*8 + (lane & 3)*2];

    #pragma unroll
    for (int am = 0; am < 2; ++am) {
        const int r0 = t0 + wm*32 + am*16 + (lane >> 2);
        #pragma unroll
        for (int half = 0; half < 2; ++half) {
            int t = r0 + half * 8;
            int b = t >> 11;
            int s = t & (SS - 1);
            size_t base = (((size_t)b*HH + h)*SS + s) * HDIM;
            if (z < 2) {
                #pragma unroll
                for (int j = 0; j < 4; ++j) {
                    int ch = j*8 + (lane & 3)*2;          // < 32
                    float v0a = acc[am][j  ][2*half]   + bia[j].x;
                    float v0b = acc[am][j  ][2*half+1] + bia[j].y;
                    float v1a = acc[am][j+4][2*half]   + bia[j+4].x;
                    float v1b = acc[am][j+4][2*half+1] + bia[j+4].y;
                    float2 c0 = *(const float2*)&cosT[s*HDIM + ch];
                    float2 s0 = *(const float2*)&sinT[s*HDIM + ch];
                    float2 c1 = *(const float2*)&cosT[s*HDIM + ch + 32];
                    float2 s1 = *(const float2*)&sinT[s*HDIM + ch + 32];
                    *(unsigned*)&df[base + ch]      = packh(v0a*c0.x - v1a*s0.x,
                                                            v0b*c0.y - v1b*s0.y);
                    *(unsigned*)&df[base + ch + 32] = packh(v1a*c1.x + v0a*s1.x,
                                                            v1b*c1.y + v0b*s1.y);
                }
            } else {
                #pragma unroll
                for (int j = 0; j < 8; ++j) {
                    int ch = j*8 + (lane & 3)*2;          // < 64
                    *(unsigned*)&df[base + ch] = packh(acc[am][j][2*half]   + bia[j].x,
                                                       acc[am][j][2*half+1] + bia[j].y);
                }
            }
        }
    }
}

// ---------------------------------------------------------------------------
// Kernel 3: output projection -> d_out [t, n] fp32. grid = (NT/128, DD/128)
// ---------------------------------------------------------------------------
__global__ __launch_bounds__(256, 2) void out_gemm(
    const float* __restrict__ bo, float* __restrict__ out)
{
    extern __shared__ __align__(16) char dsm[];
    const unsigned sbase = smem_u32(dsm);

    const int t0 = blockIdx.x * 128;
    const int n0 = blockIdx.y * 128;
    const int lane = threadIdx.x & 31;
    const int warp = threadIdx.x >> 5;
    const int wm = warp & 3, wn = warp >> 2;

    float acc[2][8][4] = {};
    run_gemm7(g_af, g_wf[3], t0, n0, sbase, acc);

    float2 bia[8];
    #pragma unroll
    for (int j = 0; j < 8; ++j)
        bia[j] = *(const float2*)&bo[n0 + wn*64 + j*8 + (lane & 3)*2];

    #pragma unroll
    for (int am = 0; am < 2; ++am) {
        const int r0 = t0 + wm*32 + am*16 + (lane >> 2);
        #pragma unroll
        for (int half = 0; half < 2; ++half) {
            int t = r0 + half * 8;
            #pragma unroll
            for (int j = 0; j < 8; ++j) {
                int n = n0 + wn*64 + j*8 + (lane & 3)*2;
                float2 o;
                o.x = acc[am][j][2*half]   + bia[j].x;
                o.y = acc[am][j][2*half+1] + bia[j].y;
                *(float2*)&out[(size_t)t*DD + n] = o;
            }
        }
    }
}

// ---------------------------------------------------------------------------
// Kernel 2: flash causal attention. 128q tile; cp.async double-buffered
// 128-key K/V superblocks; Q fragments register-cached. grid = (16, 64).
// smem: Q[128][P2] + 2 stages x (K[128][P2] + V[128][P2]) = 92160 B
// ---------------------------------------------------------------------------
#define AQ_BYTES (128*P2*2)            // 18432
#define KV_STG   (2*128*P2*2)          // 36864 (K then V)
#define ASM_TOT  (AQ_BYTES + 2*KV_STG) // 92160

__global__ __launch_bounds__(256, 2) void attn_mma()
{
    extern __shared__ __align__(16) __half smh[];
    __half* Qf = smh;                         // [128][P2]

    const int tid  = threadIdx.x;
    const int lane = tid & 31;
    const int warp = tid >> 5;
    const int bh = blockIdx.y;
    const int qt = gridDim.x - 1 - blockIdx.x;   // long tiles first
    const int q0 = qt * 128;

    const size_t hb = (size_t)bh * SS * HDIM;
    const unsigned sbase = smem_u32(smh);

    // ---- load Q tile (sync LDG once)
    #pragma unroll
    for (int p = 0; p < 4; ++p) {
        int idx = tid + p*256;
        int row = idx >> 3, c8 = idx & 7;
        *(uint4*)&Qf[row*P2 + c8*8] = *(const uint4*)&g_Qf[hb + (size_t)(q0+row)*HDIM + c8*8];
    }

    const int g = lane >> 3, lr = lane & 7;
    const unsigned adQ = sbase + (unsigned)((warp*16 + (g&1)*8 + lr)*P2 + (g>>1)*8) * 2;
    const unsigned bKoff = (unsigned)(((g&1)*8 + lr)*P2 + (g>>1)*8) * 2;

    // issue cp.async for K/V superblock kb2 into stage s
    auto issue_kv = [&](int kb2, int s) {
        const int k0s = kb2 * 128;
        const unsigned stg = sbase + AQ_BYTES + (unsigned)s * KV_STG;
        #pragma unroll
        for (int p = 0; p < 4; ++p) {
            int idx = tid + p*256;
            int row = idx >> 3, c8 = idx & 7;
            size_t go = hb + (size_t)(k0s+row)*HDIM + c8*8;
            unsigned d = stg + (unsigned)(row*P2 + c8*8)*2;
            cpa16(d, g_Kf + go);
            cpa16(d + AQ_BYTES, g_Vf + go);
        }
    };

    issue_kv(0, 0);
    CP_COMMIT();

    float O[8][4] = {};
    float m0 = -1e30f, m1 = -1e30f, l0 = 0.f, l1 = 0.f;
    const float C = 0.18033688011112042f;   // (1/8) * log2(e)

    unsigned qreg[4][4];
    bool qloaded = false;

    for (int kb2 = 0; kb2 <= qt; ++kb2) {
        const int s = kb2 & 1;
        if (kb2 < qt) {
            issue_kv(kb2 + 1, s ^ 1);
            CP_COMMIT();
            CP_WAIT(1);
        } else {
            CP_WAIT(0);
        }
        __syncthreads();

        if (!qloaded) {       // Q fragments are loop-invariant: cache once
            #pragma unroll
            for (int k16 = 0; k16 < 4; ++k16)
                ldsm4(qreg[k16], adQ + k16*32);
            qloaded = true;
        }

        const unsigned stg = sbase + AQ_BYTES + (unsigned)s * KV_STG;
        const unsigned adK = stg + bKoff;
        const unsigned adV = stg + AQ_BYTES + bKoff;

        #pragma unroll
        for (int h2 = 0; h2 < 2; ++h2) {
            const int kb = 2*kb2 + h2;
            const int k0 = kb * 64;
            const unsigned kvo = (unsigned)(h2*64*P2) * 2;

            // ---- S = Q K^T (Q from registers)
            float z[8][4] = {};
            #pragma unroll
            for (int k16 = 0; k16 < 4; ++k16) {
                #pragma unroll
                for (int jp = 0; jp < 4; ++jp) {
                    unsigned kf[4];
                    ldsm4(kf, adK + kvo + (unsigned)(jp*16*P2)*2 + k16*32);
                    MMA_F16(z[2*jp],   qreg[k16], kf[0], kf[2]);
                    MMA_F16(z[2*jp+1], qreg[k16], kf[1], kf[3]);
                }
            }

            // ---- scale (log2 domain) + causal mask (boundary blocks only)
            const bool tail = (kb >= 2*qt);
            #pragma unroll
            for (int j = 0; j < 8; ++j) {
                #pragma unroll
                for (int c = 0; c < 4; ++c) {
                    int key = k0 + j*8 + (lane & 3)*2 + (c & 1);
                    int row = q0 + warp*16 + (lane >> 2) + (c >> 1)*8;
                    z[j][c] = (tail && key > row) ? -1e30f : z[j][c]*C;
                }
            }

            // ---- online softmax
            float ml0 = -1e30f, ml1 = -1e30f;
            #pragma unroll
            for (int j = 0; j < 8; ++j) {
                ml0 = fmaxf(ml0, fmaxf(z[j][0], z[j][1]));
                ml1 = fmaxf(ml1, fmaxf(z[j][2], z[j][3]));
            }
            ml0 = fmaxf(ml0, __shfl_xor_sync(0xffffffffu, ml0, 1));
            ml0 = fmaxf(ml0, __shfl_xor_sync(0xffffffffu, ml0, 2));
            ml1 = fmaxf(ml1, __shfl_xor_sync(0xffffffffu, ml1, 1));
            ml1 = fmaxf(ml1, __shfl_xor_sync(0xffffffffu, ml1, 2));
            float mn0 = fmaxf(m0, ml0), mn1 = fmaxf(m1, ml1);
            float al0 = exp2f(m0 - mn0), al1 = exp2f(m1 - mn1);
            m0 = mn0; m1 = mn1;

            float rs0 = 0.f, rs1 = 0.f;
            #pragma unroll
            for (int j = 0; j < 8; ++j) {
                z[j][0] = exp2f(z[j][0] - mn0);
                z[j][1] = exp2f(z[j][1] - mn0);
                z[j][2] = exp2f(z[j][2] - mn1);
                z[j][3] = exp2f(z[j][3] - mn1);
                rs0 += z[j][0] + z[j][1];
                rs1 += z[j][2] + z[j][3];
            }
            rs0 += __shfl_xor_sync(0xffffffffu, rs0, 1);
            rs0 += __shfl_xor_sync(0xffffffffu, rs0, 2);
            rs1 += __shfl_xor_sync(0xffffffffu, rs1, 1);
            rs1 += __shfl_xor_sync(0xffffffffu, rs1, 2);
            l0 = l0*al0 + rs0;
            l1 = l1*al1 + rs1;
            #pragma unroll
            for (int j = 0; j < 8; ++j) {
                O[j][0] *= al0; O[j][1] *= al0;
                O[j][2] *= al1; O[j][3] *= al1;
            }

            // ---- O += P V (P packed in registers)
            #pragma unroll
            for (int k16 = 0; k16 < 4; ++k16) {
                const int f0 = 2*k16, f1 = 2*k16 + 1;
                unsigned ah[4];
                ah[0] = packh(z[f0][0], z[f0][1]);
                ah[1] = packh(z[f0][2], z[f0][3]);
                ah[2] = packh(z[f1][0], z[f1][1]);
                ah[3] = packh(z[f1][2], z[f1][3]);
                #pragma unroll
                for (int jp = 0; jp < 4; ++jp) {
                    unsigned vf[4];
                    ldsm4t(vf, adV + kvo + (unsigned)(k16*16*P2 + jp*16)*2);
                    MMA_F16(O[2*jp],   ah, vf[0], vf[1]);
                    MMA_F16(O[2*jp+1], ah, vf[2], vf[3]);
                }
            }
        }
        __syncthreads();
    }

    // ---- normalize + write att fp16 [t, d]
    const int b = bh >> 4;
    const int h = bh & 15;
    const float inv0 = 1.f / l0, inv1 = 1.f / l1;
    const int rlo = q0 + warp*16 + (lane >> 2);
    #pragma unroll
    for (int j = 0; j < 8; ++j) {
        int hd = h*HDIM + j*8 + (lane & 3)*2;
        *(unsigned*)&g_af[((size_t)(b*SS + rlo    ))*DD + hd] = packh(O[j][0]*inv0, O[j][1]*inv0);
        *(unsigned*)&g_af[((size_t)(b*SS + rlo + 8))*DD + hd] = packh(O[j][2]*inv1, O[j][3]*inv1);
    }
}

// ---------------------------------------------------------------------------
extern "C" void kernel_launch(void* const* d_in, const int* in_sizes, int n_in,
                              void* d_out, int out_size)
{
    const float* x    = (const float*)d_in[0];
    const float* cosT = (const float*)d_in[1];
    const float* sinT = (const float*)d_in[2];
    // d_in[3] = attn_mask (causal — applied analytically)
    const float* Wq = (const float*)d_in[4];
    const float* bq = (const float*)d_in[5];
    const float* Wk = (const float*)d_in[6];
    const float* bk = (const float*)d_in[7];
    const float* Wv = (const float*)d_in[8];
    const float* bv = (const float*)d_in[9];
    const float* Wo = (const float*)d_in[10];
    const float* bo = (const float*)d_in[11];
    float* out = (float*)d_out;

    // 0) fused fp32 -> fp16
    const size_t ntotal = (size_t)NT*DD + 4*(size_t)DD*DD;
    cvt_all<<<(int)(ntotal/1024), 256>>>(x, Wq, Wk, Wv, Wo);

    // 1) QKV + RoPE
    cudaFuncSetAttribute(qkv_gemm, cudaFuncAttributeMaxDynamicSharedMemorySize, GSM7);
    qkv_gemm<<<dim3(NT/128, DD/128, 3), 256, GSM7>>>(bq, bk, bv, cosT, sinT);

    // 2) causal flash attention (cp.async double-buffered KV)
    cudaFuncSetAttribute(attn_mma, cudaFuncAttributeMaxDynamicSharedMemorySize, ASM_TOT);
    attn_mma<<<dim3(SS/128, BB*HH), 256, ASM_TOT>>>();

    // 3) output projection
    cudaFuncSetAttribute(out_gemm, cudaFuncAttributeMaxDynamicSharedMemorySize, GSM7);
    out_gemm<<<dim3(NT/128, DD/128), 256, GSM7>>>(bo, out);
}